// round 3
// baseline (speedup 1.0000x reference)
#include <cuda_runtime.h>

#define NT 256
#define NW 8
#define ITILE 8
#define VS 65   // padded row stride (floats) for 64-wide tiles -> conflict-free

// shared layout (float offsets)
#define OFF_V    0        // 416 x 65 = 27040 (xr, then V in-place; rows 400..415 zeroed)
#define OFF_WV   27040    // 4096: Wv (64x64)
#define OFF_SRC  31136    // 800: s_src [2][400]
#define OFF_DST  31936    // 800: s_dst [2][400]
#define OFF_BE   32736    // 800: exp(s_dst)
#define OFF_DE   33536    // 800: exp(0.2*s_dst)
#define OFF_UW   34336    // 256: u (2x64), w (2x64)
#define OFF_SCR  34592    // 8 warps x 640 scratch (p staging / transpose)
#define SMEM_FLOATS 39712
#define SMEM_BYTES (SMEM_FLOATS * 4)

__device__ float g_uw[256];

// u[h,c] = sum_d a_src[h,d]*Wq[h*32+d, c]; w[h,c] likewise with Wk/a_dst.
__global__ void gat_prep(const float* __restrict__ Wq, const float* __restrict__ Wk,
                         const float* __restrict__ a_src, const float* __restrict__ a_dst) {
  int tid = threadIdx.x;
  int part = tid >> 6;            // 0,1: u(h0,h1); 2,3: w(h0,h1)
  int h = part & 1;
  int c = tid & 63;
  const float* W = (part < 2) ? Wq : Wk;
  const float* a = (part < 2) ? a_src : a_dst;
  float s = 0.f;
#pragma unroll
  for (int d = 0; d < 32; ++d) s += W[(h * 32 + d) * 64 + c] * a[h * 32 + d];
  g_uw[tid] = s;
}

__global__ void __launch_bounds__(NT, 1)
gat_main(const float* __restrict__ x, const float* __restrict__ Wv,
         const int* __restrict__ gso, const float* __restrict__ ln_g,
         const float* __restrict__ ln_b, float* __restrict__ out) {
  extern __shared__ float sm[];
  float* sV   = sm + OFF_V;
  float* sWv  = sm + OFF_WV;
  float* sSrc = sm + OFF_SRC;
  float* sDst = sm + OFF_DST;
  float* sBe  = sm + OFF_BE;
  float* sDe  = sm + OFF_DE;
  float* sUW  = sm + OFF_UW;
  float* sScr = sm + OFF_SCR;

  const int tid = threadIdx.x;
  const int bt = blockIdx.x;
  const int b = bt >> 5, t = bt & 31;
  const float* xbt = x + (size_t)b * 819200 + (size_t)t * 400;  // [c*12800 + n]

  for (int i = tid; i < 4096; i += NT) sWv[i] = Wv[i];
  for (int i = tid; i < 256; i += NT) sUW[i] = g_uw[i];
  for (int i = tid; i < 16 * VS; i += NT) sV[400 * VS + i] = 0.f;  // zero pad rows

  // xr[n,c] staged; gmem coalesced over n
  for (int c = 0; c < 64; ++c) {
    sV[tid * VS + c] = xbt[(size_t)c * 12800 + tid];
    int n2 = tid + NT;
    if (n2 < 400) sV[n2 * VS + c] = xbt[(size_t)c * 12800 + n2];
  }
  __syncthreads();

  // ---- Phase A: scores + in-place V projection ----
  for (int row = tid; row < 400; row += NT) {
    float xr[64];
#pragma unroll
    for (int c = 0; c < 64; ++c) xr[c] = sV[row * VS + c];

    float s0 = 0.f, s1 = 0.f, d0 = 0.f, d1 = 0.f;
#pragma unroll
    for (int c = 0; c < 64; ++c) {
      float xc = xr[c];
      s0 += xc * sUW[c];       s1 += xc * sUW[64 + c];
      d0 += xc * sUW[128 + c]; d1 += xc * sUW[192 + c];
    }
    sSrc[row] = s0;               sSrc[400 + row] = s1;
    sDst[row] = d0;               sDst[400 + row] = d1;
    sBe[row] = __expf(d0);        sBe[400 + row] = __expf(d1);
    sDe[row] = __expf(0.2f * d0); sDe[400 + row] = __expf(0.2f * d1);

    const float4* wv4 = (const float4*)sWv;
#pragma unroll 4
    for (int cp = 0; cp < 64; ++cp) {
      float a0 = 0.f, a1 = 0.f, a2 = 0.f, a3 = 0.f;
#pragma unroll
      for (int q = 0; q < 16; ++q) {
        float4 w = wv4[cp * 16 + q];   // broadcast: all threads same addr
        a0 += xr[4 * q + 0] * w.x; a1 += xr[4 * q + 1] * w.y;
        a2 += xr[4 * q + 2] * w.z; a3 += xr[4 * q + 3] * w.w;
      }
      sV[row * VS + cp] = (a0 + a1) + (a2 + a3);   // row held in regs -> safe in-place
    }
  }
  __syncthreads();

  // ---- Phase B: attention + LayerNorm + transposed store ----
  const int warp = tid >> 5, lane = tid & 31;
  float* pS = sScr + warp * 640;
  const float g0 = ln_g[lane], g1 = ln_g[32 + lane];
  const float bb0 = ln_b[lane], bb1 = ln_b[32 + lane];
  float* obase = out + (size_t)b * 819200 + (size_t)t * 400;

  for (int i0 = warp * ITILE; i0 < 400; i0 += NW * ITILE) {
    float si0[ITILE], si1[ITILE], A0[ITILE], A1[ITILE], C0[ITILE], C1[ITILE];
#pragma unroll
    for (int ii = 0; ii < ITILE; ++ii) {
      si0[ii] = sSrc[i0 + ii];         si1[ii] = sSrc[400 + i0 + ii];
      A0[ii] = __expf(si0[ii]);        A1[ii] = __expf(si1[ii]);
      C0[ii] = __expf(0.2f * si0[ii]); C1[ii] = __expf(0.2f * si1[ii]);
    }
    float acc0[ITILE], acc1[ITILE], z0[ITILE], z1[ITILE];
#pragma unroll
    for (int ii = 0; ii < ITILE; ++ii) { acc0[ii] = acc1[ii] = z0[ii] = z1[ii] = 0.f; }

    int gv[ITILE];
#pragma unroll
    for (int ii = 0; ii < ITILE; ++ii) gv[ii] = gso[(i0 + ii) * 400 + lane];

#pragma unroll 1
    for (int j0 = 0; j0 < 400; j0 += 32) {
      int j = j0 + lane;
      bool jv = j < 400;
      float dj0 = 0.f, dj1 = 0.f, Bv0 = 0.f, Bv1 = 0.f, Dv0 = 0.f, Dv1 = 0.f;
      if (jv) {
        dj0 = sDst[j]; dj1 = sDst[400 + j];
        Bv0 = sBe[j];  Bv1 = sBe[400 + j];
        Dv0 = sDe[j];  Dv1 = sDe[400 + j];
      }
      float p0[ITILE], p1[ITILE];
#pragma unroll
      for (int ii = 0; ii < ITILE; ++ii) {
        float m = (jv && gv[ii]) ? 1.f : 0.f;
        float e0 = si0[ii] + dj0;
        float e1 = si1[ii] + dj1;
        float q0 = (e0 >= 0.f) ? A0[ii] * Bv0 : C0[ii] * Dv0;  // exp(lrelu) factorized
        float q1 = (e1 >= 0.f) ? A1[ii] * Bv1 : C1[ii] * Dv1;
        p0[ii] = m * q0; p1[ii] = m * q1;
        z0[ii] += p0[ii]; z1[ii] += p1[ii];
      }
      // prefetch next gso block under the k-loop's latency
      if (j0 + 32 < 400) {
        int j2 = j0 + 32 + lane;
        bool jv2 = j2 < 400;
#pragma unroll
        for (int ii = 0; ii < ITILE; ++ii)
          gv[ii] = jv2 ? gso[(i0 + ii) * 400 + j2] : 0;
      }
      __syncwarp();
      float4* pw = (float4*)(pS + lane * 20);
      pw[0] = make_float4(p0[0], p0[1], p0[2], p0[3]);
      pw[1] = make_float4(p0[4], p0[5], p0[6], p0[7]);
      pw[2] = make_float4(p1[0], p1[1], p1[2], p1[3]);
      pw[3] = make_float4(p1[4], p1[5], p1[6], p1[7]);
      __syncwarp();
      const float* vb = sV + j0 * VS;
#pragma unroll
      for (int k = 0; k < 32; ++k) {
        float v0 = vb[k * VS + lane];        // pad rows zeroed -> no NaN from 0*garbage
        float v1 = vb[k * VS + 32 + lane];
        const float4* pr = (const float4*)(pS + k * 20);
        float4 q0 = pr[0], q0b = pr[1], q1 = pr[2], q1b = pr[3];
        acc0[0] += q0.x * v0;  acc0[1] += q0.y * v0;  acc0[2] += q0.z * v0;  acc0[3] += q0.w * v0;
        acc0[4] += q0b.x * v0; acc0[5] += q0b.y * v0; acc0[6] += q0b.z * v0; acc0[7] += q0b.w * v0;
        acc1[0] += q1.x * v1;  acc1[1] += q1.y * v1;  acc1[2] += q1.z * v1;  acc1[3] += q1.w * v1;
        acc1[4] += q1b.x * v1; acc1[5] += q1b.y * v1; acc1[6] += q1b.z * v1; acc1[7] += q1b.w * v1;
      }
      __syncwarp();
    }
    // Z across lanes (lanes partitioned j)
#pragma unroll
    for (int off = 16; off > 0; off >>= 1) {
#pragma unroll
      for (int ii = 0; ii < ITILE; ++ii) {
        z0[ii] += __shfl_xor_sync(0xffffffffu, z0[ii], off);
        z1[ii] += __shfl_xor_sync(0xffffffffu, z1[ii], off);
      }
    }
    // normalize + LayerNorm + stage transposed
#pragma unroll
    for (int ii = 0; ii < ITILE; ++ii) {
      float o0 = acc0[ii] / z0[ii];
      float o1 = acc1[ii] / z1[ii];
      float s = o0 + o1;
      float ss = o0 * o0 + o1 * o1;
#pragma unroll
      for (int off = 16; off > 0; off >>= 1) {
        s  += __shfl_xor_sync(0xffffffffu, s, off);
        ss += __shfl_xor_sync(0xffffffffu, ss, off);
      }
      float mu = s * (1.f / 64.f);
      float var = ss * (1.f / 64.f) - mu * mu;
      float rs = rsqrtf(var + 1e-5f);
      pS[lane * 9 + ii]        = (o0 - mu) * rs * g0 + bb0;   // [c][ii], stride 9
      pS[(32 + lane) * 9 + ii] = (o1 - mu) * rs * g1 + bb1;
    }
    __syncwarp();
    // coalesced transposed store: 4 channels x 8 consecutive n per iter
#pragma unroll
    for (int m = 0; m < 16; ++m) {
      int c = m * 4 + (lane >> 3);
      int ii = lane & 7;
      obase[(size_t)c * 12800 + i0 + ii] = pS[c * 9 + ii];
    }
    __syncwarp();
  }
}

extern "C" void kernel_launch(void* const* d_in, const int* in_sizes, int n_in,
                              void* d_out, int out_size) {
  const float* x      = (const float*)d_in[0];
  const float* Wq     = (const float*)d_in[1];
  const float* Wk     = (const float*)d_in[2];
  const float* Wv     = (const float*)d_in[3];
  const float* a_src  = (const float*)d_in[4];
  const float* a_dst  = (const float*)d_in[5];
  const float* ln_g   = (const float*)d_in[6];
  const float* ln_b   = (const float*)d_in[7];
  const int*   gso    = (const int*)d_in[8];
  float* out = (float*)d_out;

  cudaFuncSetAttribute(gat_main, cudaFuncAttributeMaxDynamicSharedMemorySize, SMEM_BYTES);
  gat_prep<<<1, 256>>>(Wq, Wk, a_src, a_dst);
  gat_main<<<256, NT, SMEM_BYTES>>>(x, Wv, gso, ln_g, ln_b, out);
}

// round 4
// speedup vs baseline: 1.2013x; 1.2013x over previous
#include <cuda_runtime.h>

#define NT 512
#define NW 16
#define ITILE 4
#define VS 66   // padded row stride (floats); even -> float2-aligned, 2-way bank at worst

// shared layout (float offsets)
#define OFF_V    0        // 416 x 66 = 27456 (xr then V in-place; rows 400..415 zeroed)
#define OFF_WV   27456    // 4096: Wv
#define OFF_SRC  31552    // 800: s_src [2][400]
#define OFF_DST  32352    // 800: s_dst [2][400]
#define OFF_BE   33152    // 800: exp(s_dst)
#define OFF_DE   33952    // 800: exp(0.2*s_dst)
#define OFF_UW   34752    // 256
#define OFF_SCR  35008    // 16 warps x 384
#define SMEM_FLOATS 41152
#define SMEM_BYTES (SMEM_FLOATS * 4)

__device__ float g_uw[256];

__global__ void gat_prep(const float* __restrict__ Wq, const float* __restrict__ Wk,
                         const float* __restrict__ a_src, const float* __restrict__ a_dst) {
  int tid = threadIdx.x;
  int part = tid >> 6;            // 0,1: u(h0,h1); 2,3: w(h0,h1)
  int h = part & 1;
  int c = tid & 63;
  const float* W = (part < 2) ? Wq : Wk;
  const float* a = (part < 2) ? a_src : a_dst;
  float s = 0.f;
#pragma unroll
  for (int d = 0; d < 32; ++d) s += W[(h * 32 + d) * 64 + c] * a[h * 32 + d];
  g_uw[tid] = s;
}

__global__ void __launch_bounds__(NT, 1)
gat_main(const float* __restrict__ x, const float* __restrict__ Wv,
         const int* __restrict__ gso, const float* __restrict__ ln_g,
         const float* __restrict__ ln_b, float* __restrict__ out) {
  extern __shared__ float sm[];
  float* sV   = sm + OFF_V;
  float* sWv  = sm + OFF_WV;
  float* sSrc = sm + OFF_SRC;
  float* sDst = sm + OFF_DST;
  float* sBe  = sm + OFF_BE;
  float* sDe  = sm + OFF_DE;
  float* sUW  = sm + OFF_UW;
  float* sScr = sm + OFF_SCR;

  const int tid = threadIdx.x;
  const int bt = blockIdx.x;
  const int b = bt >> 5, t = bt & 31;
  const float* xbt = x + (size_t)b * 819200 + (size_t)t * 400;  // [c*12800 + n]

  for (int i = tid; i < 4096; i += NT) sWv[i] = Wv[i];
  for (int i = tid; i < 256; i += NT) sUW[i] = g_uw[i];
  for (int i = tid; i < 16 * VS; i += NT) sV[400 * VS + i] = 0.f;  // zero pad rows

  // stage xr[n,c]; coalesced over n
  for (int idx = tid; idx < 25600; idx += NT) {
    int c = idx / 400;
    int n = idx - c * 400;
    sV[n * VS + c] = xbt[(size_t)c * 12800 + n];
  }
  __syncthreads();

  // ---- Phase A: scores + in-place V projection (1 row per thread) ----
  if (tid < 400) {
    const int row = tid;
    float xr[64];
#pragma unroll
    for (int c = 0; c < 64; ++c) xr[c] = sV[row * VS + c];

    float s0 = 0.f, s1 = 0.f, d0 = 0.f, d1 = 0.f;
#pragma unroll
    for (int c = 0; c < 64; ++c) {
      float xc = xr[c];
      s0 += xc * sUW[c];       s1 += xc * sUW[64 + c];
      d0 += xc * sUW[128 + c]; d1 += xc * sUW[192 + c];
    }
    sSrc[row] = s0;               sSrc[400 + row] = s1;
    sDst[row] = d0;               sDst[400 + row] = d1;
    sBe[row] = __expf(d0);        sBe[400 + row] = __expf(d1);
    sDe[row] = __expf(0.2f * d0); sDe[400 + row] = __expf(0.2f * d1);

    const float4* wv4 = (const float4*)sWv;
#pragma unroll 4
    for (int cp = 0; cp < 64; ++cp) {
      float a0 = 0.f, a1 = 0.f, a2 = 0.f, a3 = 0.f;
#pragma unroll
      for (int q = 0; q < 16; ++q) {
        float4 w = wv4[cp * 16 + q];   // broadcast
        a0 += xr[4 * q + 0] * w.x; a1 += xr[4 * q + 1] * w.y;
        a2 += xr[4 * q + 2] * w.z; a3 += xr[4 * q + 3] * w.w;
      }
      sV[row * VS + cp] = (a0 + a1) + (a2 + a3);   // row is in regs -> safe in-place
    }
  }
  __syncthreads();

  // ---- Phase B: attention + LayerNorm + transposed store ----
  // lane owns channels c0=2*lane, c1=2*lane+1 (both in head h = lane>=16)
  const int warp = tid >> 5, lane = tid & 31;
  float* pS = sScr + warp * 384;
  const int hsel = (lane < 16) ? 0 : 4;            // float offset into p record
  const float g0 = ln_g[2 * lane], g1 = ln_g[2 * lane + 1];
  const float bb0 = ln_b[2 * lane], bb1 = ln_b[2 * lane + 1];
  float* obase = out + (size_t)b * 819200 + (size_t)t * 400;

  for (int i0 = warp * ITILE; i0 < 400; i0 += NW * ITILE) {
    float si0[ITILE], si1[ITILE], A0[ITILE], A1[ITILE], C0[ITILE], C1[ITILE];
#pragma unroll
    for (int ii = 0; ii < ITILE; ++ii) {
      si0[ii] = sSrc[i0 + ii];         si1[ii] = sSrc[400 + i0 + ii];
      A0[ii] = __expf(si0[ii]);        A1[ii] = __expf(si1[ii]);
      C0[ii] = __expf(0.2f * si0[ii]); C1[ii] = __expf(0.2f * si1[ii]);
    }
    float accA[ITILE], accB[ITILE], z0[ITILE], z1[ITILE];
#pragma unroll
    for (int ii = 0; ii < ITILE; ++ii) { accA[ii] = accB[ii] = z0[ii] = z1[ii] = 0.f; }

    int gv[ITILE];
#pragma unroll
    for (int ii = 0; ii < ITILE; ++ii) gv[ii] = gso[(i0 + ii) * 400 + lane];

#pragma unroll 1
    for (int j0 = 0; j0 < 400; j0 += 32) {
      int j = j0 + lane;
      bool jv = j < 400;
      float dj0 = 0.f, dj1 = 0.f, Bv0 = 0.f, Bv1 = 0.f, Dv0 = 0.f, Dv1 = 0.f;
      if (jv) {
        dj0 = sDst[j]; dj1 = sDst[400 + j];
        Bv0 = sBe[j];  Bv1 = sBe[400 + j];
        Dv0 = sDe[j];  Dv1 = sDe[400 + j];
      }
      float p0[ITILE], p1[ITILE];
#pragma unroll
      for (int ii = 0; ii < ITILE; ++ii) {
        float m = (jv && gv[ii]) ? 1.f : 0.f;
        float e0 = si0[ii] + dj0;
        float e1 = si1[ii] + dj1;
        float q0 = (e0 >= 0.f) ? A0[ii] * Bv0 : C0[ii] * Dv0;  // exp(lrelu) factorized
        float q1 = (e1 >= 0.f) ? A1[ii] * Bv1 : C1[ii] * Dv1;
        p0[ii] = m * q0; p1[ii] = m * q1;
        z0[ii] += p0[ii]; z1[ii] += p1[ii];
      }
      // prefetch next gso block under the k-loop
      if (j0 + 32 < 400) {
        int j2 = j0 + 32 + lane;
        bool jv2 = j2 < 400;
#pragma unroll
        for (int ii = 0; ii < ITILE; ++ii)
          gv[ii] = jv2 ? gso[(i0 + ii) * 400 + j2] : 0;
      }
      __syncwarp();
      float4* pw = (float4*)(pS + lane * 12);     // stride 48B: conflict-free per phase
      pw[0] = make_float4(p0[0], p0[1], p0[2], p0[3]);
      pw[1] = make_float4(p1[0], p1[1], p1[2], p1[3]);
      __syncwarp();
      const float* vrow = sV + j0 * VS + 2 * lane;
#pragma unroll 8
      for (int k = 0; k < 32; ++k) {
        float2 v = *(const float2*)(vrow + k * VS);      // pad rows zeroed
        float4 pq = *(const float4*)(pS + k * 12 + hsel); // my head's p (broadcast)
        accA[0] += pq.x * v.x; accB[0] += pq.x * v.y;
        accA[1] += pq.y * v.x; accB[1] += pq.y * v.y;
        accA[2] += pq.z * v.x; accB[2] += pq.z * v.y;
        accA[3] += pq.w * v.x; accB[3] += pq.w * v.y;
      }
      __syncwarp();
    }
    // Z across lanes (lanes partitioned j)
#pragma unroll
    for (int off = 16; off > 0; off >>= 1) {
#pragma unroll
      for (int ii = 0; ii < ITILE; ++ii) {
        z0[ii] += __shfl_xor_sync(0xffffffffu, z0[ii], off);
        z1[ii] += __shfl_xor_sync(0xffffffffu, z1[ii], off);
      }
    }
    // normalize + LayerNorm + stage transposed
#pragma unroll
    for (int ii = 0; ii < ITILE; ++ii) {
      float zh = (lane < 16) ? z0[ii] : z1[ii];
      float o0 = accA[ii] / zh;
      float o1 = accB[ii] / zh;
      float s = o0 + o1;
      float ss = o0 * o0 + o1 * o1;
#pragma unroll
      for (int off = 16; off > 0; off >>= 1) {
        s  += __shfl_xor_sync(0xffffffffu, s, off);
        ss += __shfl_xor_sync(0xffffffffu, ss, off);
      }
      float mu = s * (1.f / 64.f);
      float var = ss * (1.f / 64.f) - mu * mu;
      float rs = rsqrtf(var + 1e-5f);
      pS[(2 * lane) * 5 + ii]     = (o0 - mu) * rs * g0 + bb0;  // [c][ii], stride 5
      pS[(2 * lane + 1) * 5 + ii] = (o1 - mu) * rs * g1 + bb1;
    }
    __syncwarp();
    // transposed store: groups of 4 lanes write 4 consecutive n for one c
#pragma unroll
    for (int m = 0; m < 8; ++m) {
      int idx = m * 32 + lane;
      int c = idx >> 2;
      int ii = idx & 3;
      obase[(size_t)c * 12800 + i0 + ii] = pS[c * 5 + ii];
    }
    __syncwarp();
  }
}

extern "C" void kernel_launch(void* const* d_in, const int* in_sizes, int n_in,
                              void* d_out, int out_size) {
  const float* x      = (const float*)d_in[0];
  const float* Wq     = (const float*)d_in[1];
  const float* Wk     = (const float*)d_in[2];
  const float* Wv     = (const float*)d_in[3];
  const float* a_src  = (const float*)d_in[4];
  const float* a_dst  = (const float*)d_in[5];
  const float* ln_g   = (const float*)d_in[6];
  const float* ln_b   = (const float*)d_in[7];
  const int*   gso    = (const int*)d_in[8];
  float* out = (float*)d_out;

  cudaFuncSetAttribute(gat_main, cudaFuncAttributeMaxDynamicSharedMemorySize, SMEM_BYTES);
  gat_prep<<<1, 256>>>(Wq, Wk, a_src, a_dst);
  gat_main<<<256, NT, SMEM_BYTES>>>(x, Wv, gso, ln_g, ln_b, out);
}